// round 5
// baseline (speedup 1.0000x reference)
#include <cuda_runtime.h>
#include <stdint.h>

#define NT 512
#define NWARP (NT/32)
#define HSZ 2048
#define HMASK (HSZ-1)
#define SORTN 2048
#define CCAP  2040
#define NEG_INF_F (-3.4028234663852886e38f)
#define PAD_IDX 0x7FFFFFFF

__device__ __forceinline__ uint32_t rotl32(uint32_t x, int r) {
    return (x << r) | (x >> (32 - r));
}

// JAX threefry2x32, key = jax.random.key(42) -> (k0,k1) = (0,42).
// PARTITIONABLE random_bits (jax_threefry_partitionable=True, the default):
//   counts = iota(uint64, N); bits1, bits2 = threefry2x32(key, (hi32(i), lo32(i)))
//   32-bit output = bits1 ^ bits2        (word0 XOR word1)
// Here N = B*V < 2^32 so hi32(i) = 0.
__device__ __forceinline__ float gumbel_for(uint32_t idx) {
    uint32_t x0 = 0u, x1 = idx;
    const uint32_t k0 = 0u, k1 = 42u;
    const uint32_t k2 = 0x1BD11BDAu ^ k0 ^ k1;
    x0 += k0; x1 += k1;
#define TFR(r) { x0 += x1; x1 = rotl32(x1, (r)); x1 ^= x0; }
    TFR(13) TFR(15) TFR(26) TFR(6)  x0 += k1; x1 += k2 + 1u;
    TFR(17) TFR(29) TFR(16) TFR(24) x0 += k2; x1 += k0 + 2u;
    TFR(13) TFR(15) TFR(26) TFR(6)  x0 += k0; x1 += k1 + 3u;
    TFR(17) TFR(29) TFR(16) TFR(24) x0 += k1; x1 += k2 + 4u;
    TFR(13) TFR(15) TFR(26) TFR(6)  x0 += k2; x1 += k0 + 5u;
#undef TFR
    uint32_t bits = x0 ^ x1;
    // jax.random.uniform(minval=1e-10, maxval=1.0): span rounds to exactly 1.0f
    float f = __uint_as_float((bits >> 9) | 0x3f800000u) - 1.0f;
    float u = fmaxf(1e-10f, f + 1e-10f);
    return -logf(-logf(u));
}

__device__ __forceinline__ void hash_insert(int* hkey, unsigned* hval, int tok,
                                            unsigned v, bool is_flag) {
    int h = tok & HMASK;
    while (true) {
        int prev = atomicCAS(&hkey[h], -1, tok);
        if (prev == -1 || prev == tok) {
            if (is_flag) atomicOr(&hval[h], v);
            else         atomicAdd(&hval[h], v);
            return;
        }
        h = (h + 1) & HMASK;
    }
}

__device__ __forceinline__ bool hash_find(const int* hkey, const unsigned* hval,
                                          int tok, unsigned* out) {
    int h = tok & HMASK;
    while (true) {
        int kk = hkey[h];
        if (kk == tok) { *out = hval[h]; return true; }
        if (kk == -1) { *out = 0u; return false; }
        h = (h + 1) & HMASK;
    }
}

// Exact replication of the reference pipeline arithmetic for one token.
__device__ __forceinline__ float process_val(float x, unsigned info, bool penalize,
                                             float rep, float freq, float pres,
                                             float teff) {
    unsigned cnt   = info & 0xFFFFu;
    bool in_out    = cnt != 0u;
    bool in_prompt = (info & (1u << 16)) != 0u;
    bool is_stop   = (info & (1u << 17)) != 0u;
    float v = x;
    if (penalize && is_stop) v = NEG_INF_F;
    if (in_prompt || in_out)
        v = (v > 0.0f) ? __fdiv_rn(v, rep) : __fmul_rn(v, rep);
    v = __fsub_rn(v, __fmul_rn(freq, (float)cnt));
    v = __fsub_rn(v, in_out ? pres : 0.0f);
    v = __fdiv_rn(v, teff);
    return v;
}

__global__ void __launch_bounds__(NT, 1)
sampler_kernel(const float* __restrict__ logits,
               const float* __restrict__ temperature,
               const float* __restrict__ presence,
               const float* __restrict__ frequency,
               const float* __restrict__ repetition,
               const float* __restrict__ top_p,
               const int* __restrict__ prompt_ids,
               const int* __restrict__ output_ids,
               const int* __restrict__ output_lens,
               const int* __restrict__ stop_ids,
               const int* __restrict__ min_tokens,
               const int* __restrict__ top_k,
               float* __restrict__ out,
               int B, int V, int P, int O, int S, int T)
{
    __shared__ int      hkey[HSZ];
    __shared__ unsigned hval[HSZ];
    __shared__ float    skey[SORTN];
    __shared__ int      sidx[SORTN];
    __shared__ float    redM[NWARP], redS[NWARP];
    __shared__ int      s_cnt, s_unt;
    __shared__ float    s_M, s_logS;

    const int b   = blockIdx.x;
    const int tid = threadIdx.x;

    const float temp  = temperature[b];
    const float presv = presence[b];
    const float freqv = frequency[b];
    const float repv  = repetition[b];
    const float toppv = top_p[b];
    const int   olen  = output_lens[b];
    const int   mint  = min_tokens[b];
    const bool  penalize = olen < mint;
    const float teff = (temp < 1e-5f) ? 1.0f : temp;

    // ---- build hash of touched tokens ----
    for (int i = tid; i < HSZ; i += NT) { hkey[i] = -1; hval[i] = 0u; }
    __syncthreads();
    for (int i = tid; i < P; i += NT)
        hash_insert(hkey, hval, prompt_ids[(size_t)b * P + i], 1u << 16, true);
    for (int i = tid; i < O; i += NT)
        if (i < olen)
            hash_insert(hkey, hval, output_ids[(size_t)b * O + i], 1u, false);
    for (int i = tid; i < S; i += NT)
        hash_insert(hkey, hval, stop_ids[(size_t)b * S + i], 1u << 17, true);
    __syncthreads();

    // ---- streaming scan: logsumexp (attempt 0) + candidate collection ----
    const float* row = logits + (size_t)b * V;
    float m_loc = -INFINITY, s_loc = 0.0f;
    float tcur = 3.0f;
    int cnt = 0;

    for (int attempt = 0; attempt < 8; ++attempt) {
        if (tid == 0) { s_cnt = 0; s_unt = 0; }
        __syncthreads();

        const bool do_lse = (attempt == 0);
        const int nv4 = V >> 2;
        const float4* row4 = (const float4*)row;
        for (int i = tid; i < nv4; i += NT) {
            float4 v4 = row4[i];
            float xs[4] = {v4.x, v4.y, v4.z, v4.w};
            #pragma unroll
            for (int l = 0; l < 4; ++l) {
                float x = xs[l];
                if (do_lse) {
                    if (x > m_loc) { s_loc *= __expf(m_loc - x); m_loc = x; }
                    s_loc += __expf(x - m_loc);
                }
                if (x > tcur) {
                    int p = atomicAdd(&s_cnt, 1);
                    if (p < CCAP) { skey[p] = x; sidx[p] = (i << 2) + l; }
                }
            }
        }
        for (int i = (nv4 << 2) + tid; i < V; i += NT) {
            float x = row[i];
            if (do_lse) {
                if (x > m_loc) { s_loc *= __expf(m_loc - x); m_loc = x; }
                s_loc += __expf(x - m_loc);
            }
            if (x > tcur) {
                int p = atomicAdd(&s_cnt, 1);
                if (p < CCAP) { skey[p] = x; sidx[p] = i; }
            }
        }
        __syncthreads();

        if (do_lse) {
            float m = m_loc, s = s_loc;
            #pragma unroll
            for (int off = 16; off; off >>= 1) {
                float m2 = __shfl_down_sync(0xFFFFFFFFu, m, off);
                float s2 = __shfl_down_sync(0xFFFFFFFFu, s, off);
                float mo = fmaxf(m, m2);
                s = s * __expf(m - mo) + s2 * __expf(m2 - mo);
                m = mo;
            }
            if ((tid & 31) == 0) { redM[tid >> 5] = m; redS[tid >> 5] = s; }
            __syncthreads();
            if (tid == 0) {
                float M = redM[0], Ssum = redS[0];
                for (int w = 1; w < NWARP; ++w) {
                    float m2 = redM[w], s2 = redS[w];
                    float mo = fmaxf(M, m2);
                    Ssum = Ssum * __expf(M - mo) + s2 * __expf(m2 - mo);
                    M = mo;
                }
                s_M = M; s_logS = logf(Ssum);
            }
            __syncthreads();
        }

        cnt = s_cnt;
        bool overflow = cnt > CCAP;
        if (overflow) cnt = CCAP;
        for (int j = tid; j < cnt; j += NT) {
            unsigned info;
            if (!hash_find(hkey, hval, sidx[j], &info)) atomicAdd(&s_unt, 1);
        }
        __syncthreads();
        int unt = s_unt;
        __syncthreads();
        if (overflow) { tcur += 1.0f; continue; }
        if (unt >= 68) break;
        tcur -= 1.5f;
    }

    const float sM = s_M, slogS = s_logS;

    // ---- relocate candidates to tail of pow2 region, pad front ----
    int NP = 32;
    while (NP < cnt) NP <<= 1;

    float rv[4]; int ri[4];
    #pragma unroll
    for (int r = 0; r < 4; ++r) {
        int j = tid + r * NT;
        if (j < cnt) { rv[r] = skey[j]; ri[r] = sidx[j]; }
    }
    __syncthreads();
    for (int j = tid; j < NP; j += NT) { skey[j] = -INFINITY; sidx[j] = PAD_IDX; }
    __syncthreads();
    #pragma unroll
    for (int r = 0; r < 4; ++r) {
        int j = tid + r * NT;
        if (j < cnt) { skey[NP - cnt + j] = rv[r]; sidx[NP - cnt + j] = ri[r]; }
    }
    __syncthreads();

    // ---- sort #1: raw values, (val asc, idx desc) -> read tail = lax.top_k ----
    for (int ksz = 2; ksz <= NP; ksz <<= 1) {
        for (int j = ksz >> 1; j > 0; j >>= 1) {
            for (int i = tid; i < NP; i += NT) {
                int ixj = i ^ j;
                if (ixj > i) {
                    float a = skey[i], c = skey[ixj];
                    int ai = sidx[i], ci = sidx[ixj];
                    bool gt = (a > c) || (a == c && ai < ci);
                    if (((i & ksz) == 0) ? gt : !gt) {
                        skey[i] = c; skey[ixj] = a;
                        sidx[i] = ci; sidx[ixj] = ai;
                    }
                }
            }
            __syncthreads();
        }
    }

    // top-T logprobs on raw logits
    if (tid < T) {
        float v = skey[NP - 1 - tid];
        int   ix = sidx[NP - 1 - tid];
        out[B + (size_t)b * T + tid] = __fsub_rn(__fsub_rn(v, sM), slogS);
        out[B + (size_t)B * T + (size_t)b * T + tid] = (float)ix;
    }
    __syncthreads();

    // ---- transform raw -> processed ----
    for (int j = tid; j < NP; j += NT) {
        int ix = sidx[j];
        if (ix < V) {
            unsigned info;
            hash_find(hkey, hval, ix, &info);
            skey[j] = process_val(skey[j], info, penalize, repv, freqv, presv, teff);
        }
    }
    __syncthreads();

    // ---- sort #2: processed, (val asc, idx asc) = stable argsort ----
    for (int ksz = 2; ksz <= NP; ksz <<= 1) {
        for (int j = ksz >> 1; j > 0; j >>= 1) {
            for (int i = tid; i < NP; i += NT) {
                int ixj = i ^ j;
                if (ixj > i) {
                    float a = skey[i], c = skey[ixj];
                    int ai = sidx[i], ci = sidx[ixj];
                    bool gt = (a > c) || (a == c && ai > ci);
                    if (((i & ksz) == 0) ? gt : !gt) {
                        skey[i] = c; skey[ixj] = a;
                        sidx[i] = ci; sidx[ixj] = ai;
                    }
                }
            }
            __syncthreads();
        }
    }

    // ---- serial epilogue: top-k mask, top-p mask, gumbel argmax ----
    if (tid == 0) {
        int k = top_k[b];
        if (k < 1) k = 1;
        if (k > V) k = V;
        if (k > cnt) k = cnt;

        float kth = skey[NP - k];
        int p0 = NP - k;
        while (p0 > 0 && skey[p0 - 1] == kth) --p0;  // include kth ties

        float vmax = skey[NP - 1];
        int q = NP - 1;
        while (q > 0 && skey[q - 1] == vmax) --q;    // lowest index among max ties
        int greedy = sidx[q];

        float S2 = 0.0f;
        for (int p = p0; p < NP; ++p) S2 += expf(skey[p] - vmax);

        float thr = 1.0f - toppv;
        float cum = 0.0f;
        float best = -INFINITY;
        int bestIdx = PAD_IDX;
        for (int p = p0; p < NP; ++p) {
            float pr = expf(skey[p] - vmax) / S2;
            cum += pr;
            bool drop = (cum <= thr) && (p != NP - 1);
            if (!drop) {
                uint32_t j = (uint32_t)b * (uint32_t)V + (uint32_t)sidx[p];
                float score = skey[p] + gumbel_for(j);
                if (score > best || (score == best && sidx[p] < bestIdx)) {
                    best = score; bestIdx = sidx[p];
                }
            }
        }
        int sampled = (temp < 1e-5f) ? greedy : bestIdx;
        out[b] = (float)sampled;
    }
}

extern "C" void kernel_launch(void* const* d_in, const int* in_sizes, int n_in,
                              void* d_out, int out_size) {
    const float* logits      = (const float*)d_in[0];
    const float* temperature = (const float*)d_in[1];
    const float* presence    = (const float*)d_in[2];
    const float* frequency   = (const float*)d_in[3];
    const float* repetition  = (const float*)d_in[4];
    const float* topp        = (const float*)d_in[5];
    const int*   prompt      = (const int*)d_in[6];
    const int*   outids      = (const int*)d_in[7];
    const int*   outlens     = (const int*)d_in[8];
    const int*   stops       = (const int*)d_in[9];
    const int*   mintok      = (const int*)d_in[10];
    const int*   topk        = (const int*)d_in[11];

    int B = in_sizes[1];
    int V = in_sizes[0] / B;
    int P = in_sizes[6] / B;
    int O = in_sizes[7] / B;
    int S = in_sizes[9] / B;
    int T = (out_size / B - 1) / 2;

    sampler_kernel<<<B, NT>>>(logits, temperature, presence, frequency, repetition,
                              topp, prompt, outids, outlens, stops, mintok, topk,
                              (float*)d_out, B, V, P, O, S, T);
}